// round 1
// baseline (speedup 1.0000x reference)
#include <cuda_runtime.h>
#include <math.h>

// Problem constants
#define BQ 64              // queries per CTA tile
#define BN 64              // train rows per chunk
#define NSPLIT 28          // N-direction CTA splits
#define BTOT 2048          // number of queries
#define NTRAIN 50000
#define NPAD 50048         // padded to multiple of 64
#define NCHUNK (NPAD / BN) // 782
#define CDIM 16

// Scratch (device globals: allocation-free per harness rules)
__device__ float g_tsq[NPAD];
__device__ float g_xsq[BTOT];
__device__ float g_pp[NSPLIT * BTOT * CDIM];
__device__ float g_ws[NSPLIT * BTOT];

// ---------------------------------------------------------------------------
// Pass 0: squared norms. tsq padded with +inf so padded rows get weight 0.
// ---------------------------------------------------------------------------
__global__ void k_pre(const float* __restrict__ x, const float* __restrict__ trx) {
    int i = blockIdx.x * blockDim.x + threadIdx.x;
    if (i < NPAD) {
        float s = INFINITY;
        if (i < NTRAIN) {
            const float4* r = (const float4*)(trx + (size_t)i * 64);
            s = 0.f;
#pragma unroll
            for (int k = 0; k < 16; k++) {
                float4 v = r[k];
                s += v.x * v.x + v.y * v.y + v.z * v.z + v.w * v.w;
            }
        }
        g_tsq[i] = s;
    }
    if (i < BTOT) {
        const float4* r = (const float4*)(x + (size_t)i * 64);
        float s = 0.f;
#pragma unroll
        for (int k = 0; k < 16; k++) {
            float4 v = r[k];
            s += v.x * v.x + v.y * v.y + v.z * v.z + v.w * v.w;
        }
        g_xsq[i] = s;
    }
}

// ---------------------------------------------------------------------------
// Pass 1: fused cross-GEMM + exp + weighted-sum GEMM over an N slice.
//   CTA: 64 queries x (chunks j = blockIdx.y, step NSPLIT), 256 threads.
//   GEMM1: 4x4 micro-tile, float4 k-vector loads, XOR-swizzled smem.
//   GEMM2: thread = (q, c4), pred accumulates in 4 registers across chunks.
// ---------------------------------------------------------------------------
__global__ __launch_bounds__(256) void k_main(const float* __restrict__ x,
                                              const float* __restrict__ trx,
                                              const float* __restrict__ trY) {
    __shared__ float4 sA[BQ * 16];  // x tile   [m][kq ^ (m&15)]
    __shared__ float4 sB[BN * 16];  // t tile   [n][kq ^ (n&15)]   (aliased as W)
    __shared__ float4 sY[BN * 4];   // y tile   [n][c4]
    float* sWf = (float*)sB;        // W tile   [m*64 + (n ^ (m&15))]

    const int t = threadIdx.x;
    const int mbase = blockIdx.x * BQ;
    const int s = blockIdx.y;
    const int tx = t & 15, ty = t >> 4;

    // Load + swizzle x tile (once per CTA), coalesced float4
#pragma unroll
    for (int i = 0; i < 4; i++) {
        int e = t + i * 256;
        int kq = e & 15, m = e >> 4;
        sA[m * 16 + (kq ^ (m & 15))] =
            *(const float4*)(x + (size_t)(mbase + m) * 64 + kq * 4);
    }

    float xsq[4];
#pragma unroll
    for (int i = 0; i < 4; i++) xsq[i] = g_xsq[mbase + ty + 16 * i];

    float ws[4] = {0.f, 0.f, 0.f, 0.f};
    float4 pred = make_float4(0.f, 0.f, 0.f, 0.f);
    const int q = t >> 2, c4 = t & 3;
    const int qx = q & 15;

    for (int j = s; j < NCHUNK; j += NSPLIT) {
        const int nbase = j * BN;
        __syncthreads();  // prior GEMM2 done with sW(=sB)/sY before reload

        // Load train_x chunk (swizzled) and train_y chunk, zero-fill tail
#pragma unroll
        for (int i = 0; i < 4; i++) {
            int e = t + i * 256;
            int kq = e & 15, n = e >> 4;
            int gn = nbase + n;
            float4 v = make_float4(0.f, 0.f, 0.f, 0.f);
            if (gn < NTRAIN) v = *(const float4*)(trx + (size_t)gn * 64 + kq * 4);
            sB[n * 16 + (kq ^ (n & 15))] = v;
        }
        {
            int n = t >> 2, cc = t & 3;
            int gn = nbase + n;
            float4 v = make_float4(0.f, 0.f, 0.f, 0.f);
            if (gn < NTRAIN) v = *(const float4*)(trY + (size_t)gn * 16 + cc * 4);
            sY[n * 4 + cc] = v;
        }
        __syncthreads();

        // GEMM1: cross[m][n], m = ty+16i, n = tx+16j
        float c[4][4];
#pragma unroll
        for (int i = 0; i < 4; i++)
#pragma unroll
            for (int jj = 0; jj < 4; jj++) c[i][jj] = 0.f;

#pragma unroll
        for (int kq = 0; kq < 16; kq++) {
            float4 a[4], b[4];
#pragma unroll
            for (int i = 0; i < 4; i++)
                a[i] = sA[(ty + 16 * i) * 16 + (kq ^ ty)];
#pragma unroll
            for (int jj = 0; jj < 4; jj++)
                b[jj] = sB[(tx + 16 * jj) * 16 + (kq ^ tx)];
#pragma unroll
            for (int i = 0; i < 4; i++)
#pragma unroll
                for (int jj = 0; jj < 4; jj++) {
                    c[i][jj] += a[i].x * b[jj].x;
                    c[i][jj] += a[i].y * b[jj].y;
                    c[i][jj] += a[i].z * b[jj].z;
                    c[i][jj] += a[i].w * b[jj].w;
                }
        }
        __syncthreads();  // all threads done reading sB before overwrite as W

        // Fused epilogue: weights + row-sum + store W tile (swizzled)
#pragma unroll
        for (int jj = 0; jj < 4; jj++) {
            int n = tx + 16 * jj;
            float tsq = g_tsq[nbase + n];
#pragma unroll
            for (int i = 0; i < 4; i++) {
                float dn = 2.f * c[i][jj] - xsq[i] - tsq;  // = -distance
                float w = __expf(dn * 0.005f);             // exp(-d / (2*sigma^2))
                ws[i] += w;
                sWf[(ty + 16 * i) * 64 + (n ^ ty)] = w;
            }
        }
        __syncthreads();

        // GEMM2: pred[q][c4] += sum_n W[q][n] * Y[n][c4]
#pragma unroll 8
        for (int n = 0; n < 64; n++) {
            float w = sWf[q * 64 + (n ^ qx)];
            float4 y = sY[n * 4 + c4];
            pred.x += w * y.x;
            pred.y += w * y.y;
            pred.z += w * y.z;
            pred.w += w * y.w;
        }
    }

    // Write pred partials (unique (s, q, c4) per thread -> direct float4 store)
    *(float4*)(g_pp + ((size_t)(s * BTOT + mbase + q)) * CDIM + c4 * 4) = pred;

    // Reduce weight row-sums across the 16 tx lanes (lanes 0-15 / 16-31)
#pragma unroll
    for (int off = 8; off; off >>= 1)
#pragma unroll
        for (int i = 0; i < 4; i++)
            ws[i] += __shfl_down_sync(0xffffffffu, ws[i], off, 16);
    if (tx == 0) {
#pragma unroll
        for (int i = 0; i < 4; i++)
            g_ws[s * BTOT + mbase + ty + 16 * i] = ws[i];
    }
}

// ---------------------------------------------------------------------------
// Pass 2: reduce N-split partials, normalize.
// ---------------------------------------------------------------------------
__global__ void k_fin(float* __restrict__ out) {
    int i = blockIdx.x * blockDim.x + threadIdx.x;
    if (i >= BTOT * CDIM) return;
    int qd = i >> 4;
    float acc = 0.f, wsum = 0.f;
#pragma unroll
    for (int s = 0; s < NSPLIT; s++) {
        acc += g_pp[(size_t)s * BTOT * CDIM + i];
        wsum += g_ws[s * BTOT + qd];
    }
    out[i] = acc / (wsum + 1e-10f);
}

extern "C" void kernel_launch(void* const* d_in, const int* in_sizes, int n_in,
                              void* d_out, int out_size) {
    const float* x   = (const float*)d_in[0];
    const float* trx = (const float*)d_in[1];
    const float* trY = (const float*)d_in[2];
    float* out = (float*)d_out;

    k_pre<<<(NPAD + 255) / 256, 256>>>(x, trx);
    dim3 grid(BTOT / BQ, NSPLIT);
    k_main<<<grid, 256>>>(x, trx, trY);
    k_fin<<<(BTOT * CDIM + 255) / 256, 256>>>(out);
}